// round 1
// baseline (speedup 1.0000x reference)
#include <cuda_runtime.h>
#include <cuda_bf16.h>
#include <cstdio>

// GraphConv: out = relu( ((A @ X + X) / (rowsum(A)+1)) @ W )
// A: [B, N, N] f32, X: [B, N, F] f32, W: [F, F] f32, out: [B, N, F] f32
// B=4, N=4096, F=128.

#define Bn   4
#define Nn   4096
#define Fn   128
#define MT   128      // rows per CTA
#define KT   16       // k-chunk
#define NTHR 512

// smem layout (floats):
// As   [128][17]   = 2176
// Xs   [16][128]   = 2048
// degp [128][4]    = 512
// Ys   [128][129]  = 16512
// Ws   [128][128]  = 16384
#define AS_OFF   0
#define XS_OFF   (AS_OFF + 128*17)
#define DEGP_OFF (XS_OFF + 16*128)
#define YS_OFF   (DEGP_OFF + 128*4)
#define WS_OFF   (YS_OFF + 128*129)
#define SMEM_FLOATS (WS_OFF + 128*128)

__global__ __launch_bounds__(NTHR, 1)
void graphconv_fused_kernel(const float* __restrict__ A,
                            const float* __restrict__ X,
                            const float* __restrict__ W,
                            float* __restrict__ out)
{
    extern __shared__ float sm[];
    float* As   = sm + AS_OFF;    // [128][17] padded
    float* Xs   = sm + XS_OFF;    // [16][128]
    float* degp = sm + DEGP_OFF;  // [128][4]
    float* Ys   = sm + YS_OFF;    // [128][129] padded
    float* Ws   = sm + WS_OFF;    // [128][128]

    const int b  = blockIdx.y;
    const int r0 = blockIdx.x * MT;
    const int tid = threadIdx.x;

    // micro-tile: 4 rows x 8 cols per thread
    const int ty = tid >> 4;     // 0..31 -> rows ty*4 .. ty*4+3
    const int tx = tid & 15;     // 0..15 -> cols tx*8 .. tx*8+7

    // A-tile loading role: one float4 per thread per chunk
    const int arow = tid >> 2;   // 0..127
    const int akv  = tid & 3;    // 0..3  (which float4 within 16-wide chunk)

    // X-tile loading role
    const int xrow = tid >> 5;   // 0..15
    const int xcv  = tid & 31;   // 0..31 (float4 within 128-wide row)

    const float* Ab = A + (size_t)b * Nn * Nn;
    const float* Xb = X + (size_t)b * Nn * Fn;

    float acc[4][8];
#pragma unroll
    for (int i = 0; i < 4; i++)
#pragma unroll
        for (int j = 0; j < 8; j++) acc[i][j] = 0.0f;

    float degloc = 0.0f;

    const float* Arow_ptr = Ab + (size_t)(r0 + arow) * Nn + akv * 4;

    for (int k0 = 0; k0 < Nn; k0 += KT) {
        // --- load A tile [128][16] + accumulate deg ---
        float4 av = *(const float4*)(Arow_ptr + k0);
        degloc += av.x + av.y + av.z + av.w;
        {
            float* dst = As + arow * 17 + akv * 4;
            dst[0] = av.x; dst[1] = av.y; dst[2] = av.z; dst[3] = av.w;
        }
        // --- load X tile [16][128] ---
        float4 xv = *(const float4*)(Xb + (size_t)(k0 + xrow) * Fn + xcv * 4);
        *(float4*)(Xs + xrow * 128 + xcv * 4) = xv;

        __syncthreads();

#pragma unroll
        for (int k = 0; k < KT; k++) {
            float a0 = As[(ty * 4 + 0) * 17 + k];
            float a1 = As[(ty * 4 + 1) * 17 + k];
            float a2 = As[(ty * 4 + 2) * 17 + k];
            float a3 = As[(ty * 4 + 3) * 17 + k];
            float4 x0 = *(const float4*)(Xs + k * 128 + tx * 8);
            float4 x1 = *(const float4*)(Xs + k * 128 + tx * 8 + 4);
            float xr[8] = {x0.x, x0.y, x0.z, x0.w, x1.x, x1.y, x1.z, x1.w};
#pragma unroll
            for (int j = 0; j < 8; j++) {
                acc[0][j] = fmaf(a0, xr[j], acc[0][j]);
                acc[1][j] = fmaf(a1, xr[j], acc[1][j]);
                acc[2][j] = fmaf(a2, xr[j], acc[2][j]);
                acc[3][j] = fmaf(a3, xr[j], acc[3][j]);
            }
        }
        __syncthreads();
    }

    // --- reduce deg partials ---
    degp[arow * 4 + akv] = degloc;
    __syncthreads();

    // --- y = (A@X + X) / (deg+1) into smem; also stage W into smem ---
#pragma unroll
    for (int i = 0; i < 4; i++) {
        int row = ty * 4 + i;
        float deg = degp[row * 4 + 0] + degp[row * 4 + 1] +
                    degp[row * 4 + 2] + degp[row * 4 + 3] + 1.0f;
        float rinv = 1.0f / deg;
        const float* xg = Xb + (size_t)(r0 + row) * Fn + tx * 8;
        float4 g0 = *(const float4*)(xg);
        float4 g1 = *(const float4*)(xg + 4);
        float* yd = Ys + row * 129 + tx * 8;
        yd[0] = (acc[i][0] + g0.x) * rinv;
        yd[1] = (acc[i][1] + g0.y) * rinv;
        yd[2] = (acc[i][2] + g0.z) * rinv;
        yd[3] = (acc[i][3] + g0.w) * rinv;
        yd[4] = (acc[i][4] + g1.x) * rinv;
        yd[5] = (acc[i][5] + g1.y) * rinv;
        yd[6] = (acc[i][6] + g1.z) * rinv;
        yd[7] = (acc[i][7] + g1.w) * rinv;
    }
    // W: 16384 floats = 4096 float4, 512 threads -> 8 each
#pragma unroll
    for (int idx = tid; idx < 4096; idx += NTHR)
        ((float4*)Ws)[idx] = ((const float4*)W)[idx];

    __syncthreads();

    // --- second GEMM: z = y @ W, relu, store ---
    float acc2[4][8];
#pragma unroll
    for (int i = 0; i < 4; i++)
#pragma unroll
        for (int j = 0; j < 8; j++) acc2[i][j] = 0.0f;

#pragma unroll 4
    for (int k = 0; k < Fn; k++) {
        float a0 = Ys[(ty * 4 + 0) * 129 + k];
        float a1 = Ys[(ty * 4 + 1) * 129 + k];
        float a2 = Ys[(ty * 4 + 2) * 129 + k];
        float a3 = Ys[(ty * 4 + 3) * 129 + k];
        float4 w0 = *(const float4*)(Ws + k * 128 + tx * 8);
        float4 w1 = *(const float4*)(Ws + k * 128 + tx * 8 + 4);
        float wr[8] = {w0.x, w0.y, w0.z, w0.w, w1.x, w1.y, w1.z, w1.w};
#pragma unroll
        for (int j = 0; j < 8; j++) {
            acc2[0][j] = fmaf(a0, wr[j], acc2[0][j]);
            acc2[1][j] = fmaf(a1, wr[j], acc2[1][j]);
            acc2[2][j] = fmaf(a2, wr[j], acc2[2][j]);
            acc2[3][j] = fmaf(a3, wr[j], acc2[3][j]);
        }
    }

#pragma unroll
    for (int i = 0; i < 4; i++) {
        int row = ty * 4 + i;
        float* og = out + ((size_t)b * Nn + (r0 + row)) * Fn + tx * 8;
        float4 o0, o1;
        o0.x = fmaxf(acc2[i][0], 0.0f);
        o0.y = fmaxf(acc2[i][1], 0.0f);
        o0.z = fmaxf(acc2[i][2], 0.0f);
        o0.w = fmaxf(acc2[i][3], 0.0f);
        o1.x = fmaxf(acc2[i][4], 0.0f);
        o1.y = fmaxf(acc2[i][5], 0.0f);
        o1.z = fmaxf(acc2[i][6], 0.0f);
        o1.w = fmaxf(acc2[i][7], 0.0f);
        *(float4*)(og)     = o0;
        *(float4*)(og + 4) = o1;
    }
}

extern "C" void kernel_launch(void* const* d_in, const int* in_sizes, int n_in,
                              void* d_out, int out_size)
{
    const float* A = (const float*)d_in[0];  // [B, N, N]
    const float* X = (const float*)d_in[1];  // [B, N, F]
    const float* W = (const float*)d_in[2];  // [F, F]
    float* out = (float*)d_out;

    static bool attr_set = false;
    if (!attr_set) {
        cudaFuncSetAttribute(graphconv_fused_kernel,
                             cudaFuncAttributeMaxDynamicSharedMemorySize,
                             SMEM_FLOATS * sizeof(float));
        attr_set = true;
    }

    dim3 grid(Nn / MT, Bn);
    graphconv_fused_kernel<<<grid, NTHR, SMEM_FLOATS * sizeof(float)>>>(A, X, W, out);
}

// round 3
// speedup vs baseline: 5.3083x; 5.3083x over previous
#include <cuda_runtime.h>
#include <cstdint>

// GraphConv: out = relu( ((A @ X + X) / (rowsum(A)+1)) @ W )
// A: [4,4096,4096] f32, X: [4,4096,128] f32, W: [128,128] f32, out f32.
// mma.sync tf32 path (compute_103-portable; tcgen05 unavailable at this vISA).

#define Bn 4
#define Nn 4096
#define Fn 128
#define KT 32                // k per pipeline tile
#define NTILES (Nn / KT)     // 128
#define STAGES 4
#define NTHR 256

// device scratch: X^T per batch [f][k], W^T [n][k]
__device__ __align__(256) float Xt_g[(size_t)Bn * Fn * Nn];
__device__ __align__(256) float Wt_g[Fn * Fn];

// smem: 4 stages x (A tile 16KB + Xt tile 16KB) + W 64KB + deg 512B
#define STAGE_B    32768
#define WS_OFF     (STAGES * STAGE_B)    // 131072
#define DEG_OFF    (WS_OFF + 65536)      // 196608
#define SMEM_TOTAL (DEG_OFF + 512)       // 197120

#define SW(x) ((x) ^ (((x) >> 3) & 0x70))

__device__ __forceinline__ uint32_t smem_u32(const void* p) {
    uint32_t a;
    asm("{ .reg .u64 t; cvta.to.shared.u64 t, %1; cvt.u32.u64 %0, t; }" : "=r"(a) : "l"(p));
    return a;
}
__device__ __forceinline__ void cp16(uint32_t dst, const void* src) {
    asm volatile("cp.async.cg.shared.global [%0], [%1], 16;" :: "r"(dst), "l"(src) : "memory");
}
__device__ __forceinline__ void ldsm4(uint32_t* r, uint32_t a) {
    asm volatile("ldmatrix.sync.aligned.m8n8.x4.shared.b16 {%0,%1,%2,%3}, [%4];"
                 : "=r"(r[0]), "=r"(r[1]), "=r"(r[2]), "=r"(r[3]) : "r"(a));
}
__device__ __forceinline__ uint32_t f2tf(uint32_t x) {
    uint32_t d;
    asm("cvt.rna.tf32.f32 %0, %1;" : "=r"(d) : "f"(__uint_as_float(x)));
    return d;
}
__device__ __forceinline__ void mma8(float* c, const uint32_t* a, const uint32_t* b) {
    asm volatile(
        "mma.sync.aligned.m16n8k8.row.col.f32.tf32.tf32.f32 "
        "{%0,%1,%2,%3},{%4,%5,%6,%7},{%8,%9},{%0,%1,%2,%3};"
        : "+f"(c[0]), "+f"(c[1]), "+f"(c[2]), "+f"(c[3])
        : "r"(a[0]), "r"(a[1]), "r"(a[2]), "r"(a[3]), "r"(b[0]), "r"(b[1]));
}

// ===================== prep kernels =====================
__global__ void prep_xt(const float* __restrict__ X) {
    __shared__ float t[32][33];
    int b = blockIdx.z;
    int bk = blockIdx.x * 32;   // node (k) tile
    int bn = blockIdx.y * 32;   // feature (n) tile
    int tx = threadIdx.x, ty = threadIdx.y;   // 32 x 8
    const float* Xb = X + (size_t)b * Nn * Fn;
    float* Xtb = Xt_g + (size_t)b * Fn * Nn;
#pragma unroll
    for (int i = 0; i < 4; i++)
        t[ty + i * 8][tx] = Xb[(size_t)(bk + ty + i * 8) * Fn + bn + tx];
    __syncthreads();
#pragma unroll
    for (int i = 0; i < 4; i++)
        Xtb[(size_t)(bn + ty + i * 8) * Nn + bk + tx] = t[tx][ty + i * 8];
}

__global__ void prep_wt(const float* __restrict__ W) {
    __shared__ float t[32][33];
    int bk = blockIdx.x * 32, bn = blockIdx.y * 32;
    int tx = threadIdx.x, ty = threadIdx.y;
#pragma unroll
    for (int i = 0; i < 4; i++)
        t[ty + i * 8][tx] = W[(size_t)(bk + ty + i * 8) * Fn + bn + tx];
    __syncthreads();
#pragma unroll
    for (int i = 0; i < 4; i++)
        Wt_g[(size_t)(bn + ty + i * 8) * Fn + bk + tx] = t[tx][ty + i * 8];
}

// ===================== main kernel =====================
__global__ __launch_bounds__(NTHR, 1)
void graphconv_mma_kernel(const float* __restrict__ A,
                          const float* __restrict__ X,
                          float* __restrict__ out)
{
    extern __shared__ char smem[];
    const uint32_t sb = smem_u32(smem);
    const int tid = threadIdx.x;
    const int w = tid >> 5, L = tid & 31;
    const int b = blockIdx.y, r0 = blockIdx.x * 128;

    // warp tile: 64m x 32n ; warps arranged 2(m) x 4(n)
    const int mw = (w >> 2) * 64;
    const int nw = (w & 3) * 32;
    const int mat = L >> 3, ro = L & 7, g = L >> 2, tg = L & 3;
    // ldmatrix per-lane offsets: A quadrants (rows split, then k halves)
    const int aro = ro + (mat & 1) * 8, aco = (mat >> 1) * 16;
    // B quadrants (k halves first, then n split)
    const int bro = ro + (mat >> 1) * 8, bco = (mat & 1) * 16;

    const float* Abase = A + ((size_t)b * Nn + r0) * Nn;
    const float* Xtb   = Xt_g + (size_t)b * Fn * Nn;

    float acc[16][4];
#pragma unroll
    for (int i = 0; i < 16; i++)
#pragma unroll
        for (int j = 0; j < 4; j++) acc[i][j] = 0.0f;

    float degacc[8];
#pragma unroll
    for (int j = 0; j < 8; j++) degacc[j] = 0.0f;

    auto load_tile = [&](int t) {
        const int s = t & (STAGES - 1);
        const int k0 = t * KT;
        const uint32_t sA = sb + s * STAGE_B;
        const uint32_t sX = sA + 16384;
#pragma unroll
        for (int i = 0; i < 4; i++) {
            int c = tid + i * NTHR;           // 0..1023
            int row = c >> 3, j = c & 7;
            cp16(sA + SW(row * 128 + j * 16), Abase + (size_t)row * Nn + k0 + j * 4);
        }
#pragma unroll
        for (int i = 0; i < 4; i++) {
            int c = tid + i * NTHR;
            int row = c >> 3, j = c & 7;
            cp16(sX + SW(row * 128 + j * 16), Xtb + (size_t)row * Nn + k0 + j * 4);
        }
    };

    auto compute_tile = [&](int s) {
        const uint32_t aA = sb + s * STAGE_B;
        const uint32_t aX = aA + 16384;
#pragma unroll
        for (int st = 0; st < 4; st++) {
            const int kb = st * 32;
            uint32_t af[4][4];
#pragma unroll
            for (int mt = 0; mt < 4; mt++)
                ldsm4(af[mt], aA + SW((mw + mt * 16 + aro) * 128 + kb + aco));
            uint32_t bf[4][2];
#pragma unroll
            for (int ntp = 0; ntp < 2; ntp++) {
                uint32_t r[4];
                ldsm4(r, aX + SW((nw + ntp * 16 + bro) * 128 + kb + bco));
                bf[ntp * 2][0]     = f2tf(r[0]);
                bf[ntp * 2][1]     = f2tf(r[1]);
                bf[ntp * 2 + 1][0] = f2tf(r[2]);
                bf[ntp * 2 + 1][1] = f2tf(r[3]);
            }
            if (nw == 0) {  // deg accumulated in exact f32 from pre-cvt A frags
#pragma unroll
                for (int mt = 0; mt < 4; mt++) {
                    degacc[mt * 2]     += __uint_as_float(af[mt][0]) + __uint_as_float(af[mt][2]);
                    degacc[mt * 2 + 1] += __uint_as_float(af[mt][1]) + __uint_as_float(af[mt][3]);
                }
            }
#pragma unroll
            for (int mt = 0; mt < 4; mt++) {
#pragma unroll
                for (int i = 0; i < 4; i++) af[mt][i] = f2tf(af[mt][i]);
#pragma unroll
                for (int nt = 0; nt < 4; nt++)
                    mma8(acc[mt * 4 + nt], af[mt], bf[nt]);
            }
        }
    };

    // ---- pipeline ----
#pragma unroll
    for (int t = 0; t < STAGES - 1; t++) {
        load_tile(t);
        asm volatile("cp.async.commit_group;" ::: "memory");
    }
    for (int t = 0; t < NTILES; t++) {
        asm volatile("cp.async.wait_group 2;" ::: "memory");
        __syncthreads();
        if (t + STAGES - 1 < NTILES) load_tile(t + STAGES - 1);
        asm volatile("cp.async.commit_group;" ::: "memory");
        compute_tile(t & (STAGES - 1));
    }
    __syncthreads();

    // ---- deg reduce across tg lanes -> smem ----
    float* degp = (float*)(smem + (DEG_OFF - 0));
    if (nw == 0) {
#pragma unroll
        for (int j = 0; j < 8; j++) {
            float v = degacc[j];
            v += __shfl_xor_sync(0xffffffffu, v, 1);
            v += __shfl_xor_sync(0xffffffffu, v, 2);
            if (tg == 0) degp[mw + (j >> 1) * 16 + g + (j & 1) * 8] = v;
        }
    }

    // ---- W^T -> smem (4 k-tiles of [128n][32k], SW128) ----
#pragma unroll
    for (int i = 0; i < 16; i++) {
        int c = tid + i * NTHR;               // 0..4095
        int n = c >> 5, j = c & 31;
        cp16(sb + WS_OFF + (j >> 3) * 16384 + SW(n * 128 + (j & 7) * 16),
             Wt_g + (size_t)n * Fn + j * 4);
    }
    asm volatile("cp.async.commit_group;" ::: "memory");
    asm volatile("cp.async.wait_group 0;" ::: "memory");
    __syncthreads();

    // ---- y = (ax + X) / (deg + 1) -> smem (4 k-tiles at sb+0) ----
#pragma unroll
    for (int mt = 0; mt < 4; mt++) {
        int m1 = mw + mt * 16 + g, m2 = m1 + 8;
        float r1 = 1.0f / (degp[m1] + 1.0f);
        float r2 = 1.0f / (degp[m2] + 1.0f);
        const float* x1 = X + ((size_t)b * Nn + r0 + m1) * Fn;
        const float* x2 = X + ((size_t)b * Nn + r0 + m2) * Fn;
#pragma unroll
        for (int nt = 0; nt < 4; nt++) {
            int n = nw + nt * 8 + 2 * tg;
            float* c = acc[mt * 4 + nt];
            float2 xa = *(const float2*)(x1 + n);
            float2 xb = *(const float2*)(x2 + n);
            float y0 = (c[0] + xa.x) * r1, y1 = (c[1] + xa.y) * r1;
            float y2 = (c[2] + xb.x) * r2, y3 = (c[3] + xb.y) * r2;
            uint32_t base = sb + (n >> 5) * 16384;
            asm volatile("st.shared.v2.f32 [%0], {%1,%2};"
                         :: "r"(base + SW(m1 * 128 + (n & 31) * 4)), "f"(y0), "f"(y1) : "memory");
            asm volatile("st.shared.v2.f32 [%0], {%1,%2};"
                         :: "r"(base + SW(m2 * 128 + (n & 31) * 4)), "f"(y2), "f"(y3) : "memory");
        }
    }
    __syncthreads();

    // ---- second GEMM: z = y @ W  (M=128,N=128,K=128) ----
    float acc2[16][4];
#pragma unroll
    for (int i = 0; i < 16; i++)
#pragma unroll
        for (int j = 0; j < 4; j++) acc2[i][j] = 0.0f;

#pragma unroll
    for (int st = 0; st < 16; st++) {
        const uint32_t aY = sb + (st >> 2) * 16384;
        const uint32_t aW = sb + WS_OFF + (st >> 2) * 16384;
        const int kb = (st & 3) * 32;
        uint32_t af[4][4];
#pragma unroll
        for (int mt = 0; mt < 4; mt++)
            ldsm4(af[mt], aY + SW((mw + mt * 16 + aro) * 128 + kb + aco));
        uint32_t bf[4][2];
#pragma unroll
        for (int ntp = 0; ntp < 2; ntp++) {
            uint32_t r[4];
            ldsm4(r, aW + SW((nw + ntp * 16 + bro) * 128 + kb + bco));
            bf[ntp * 2][0]     = f2tf(r[0]);
            bf[ntp * 2][1]     = f2tf(r[1]);
            bf[ntp * 2 + 1][0] = f2tf(r[2]);
            bf[ntp * 2 + 1][1] = f2tf(r[3]);
        }
#pragma unroll
        for (int mt = 0; mt < 4; mt++) {
#pragma unroll
            for (int i = 0; i < 4; i++) af[mt][i] = f2tf(af[mt][i]);
#pragma unroll
            for (int nt = 0; nt < 4; nt++)
                mma8(acc2[mt * 4 + nt], af[mt], bf[nt]);
        }
    }

    // ---- relu + store ----
#pragma unroll
    for (int mt = 0; mt < 4; mt++) {
        int m1 = mw + mt * 16 + g, m2 = m1 + 8;
        float* o1 = out + ((size_t)b * Nn + r0 + m1) * Fn;
        float* o2 = out + ((size_t)b * Nn + r0 + m2) * Fn;
#pragma unroll
        for (int nt = 0; nt < 4; nt++) {
            int n = nw + nt * 8 + 2 * tg;
            float* c = acc2[mt * 4 + nt];
            *(float2*)(o1 + n) = make_float2(fmaxf(c[0], 0.0f), fmaxf(c[1], 0.0f));
            *(float2*)(o2 + n) = make_float2(fmaxf(c[2], 0.0f), fmaxf(c[3], 0.0f));
        }
    }
}

// ===================== launch =====================
extern "C" void kernel_launch(void* const* d_in, const int* in_sizes, int n_in,
                              void* d_out, int out_size)
{
    const float* A = (const float*)d_in[0];
    const float* X = (const float*)d_in[1];
    const float* W = (const float*)d_in[2];
    float* out = (float*)d_out;

    static bool attr_set = false;
    if (!attr_set) {
        cudaFuncSetAttribute(graphconv_mma_kernel,
                             cudaFuncAttributeMaxDynamicSharedMemorySize, SMEM_TOTAL);
        attr_set = true;
    }

    dim3 tb(32, 8);
    prep_xt<<<dim3(Nn / 32, Fn / 32, Bn), tb>>>(X);
    prep_wt<<<dim3(Fn / 32, Fn / 32), tb>>>(W);

    dim3 grid(Nn / 128, Bn);
    graphconv_mma_kernel<<<grid, NTHR, SMEM_TOTAL>>>(A, X, out);
}